// round 16
// baseline (speedup 1.0000x reference)
#include <cuda_runtime.h>
#include <cuda_bf16.h>

#define FULLMASK 0xffffffffu

namespace {
constexpr int B = 64;
constexpr int T = 32768;
constexpr int R = 16;
}

// Scratch: hidden states for all steps, layout [B][T][R] (contiguous per step).
__device__ float g_hs[(size_t)B * T * R];   // 128 MiB

__device__ __forceinline__ float lrelu(float v) { return v >= 0.f ? v : 0.1f * v; }
__device__ __forceinline__ float tanh_fast(float v) {
    float r;
    asm("tanh.approx.f32 %0, %1;" : "=f"(r) : "f"(v));
    return r;
}

// One warp per sample. Lane (g, j): g = lane>>4, j = lane&15.
// Lane owns hidden unit j; half g sums k = 8g..8g+7 of each gate (split-k),
// halves combined with one shfl_xor(16) per gate.
// Single 8-deep FMA chain per gate: gathered operands arrive serially, so the
// chain is arrival-limited anyway; deletes the 2-acc combine adds (3 ops/step)
// and finishes 4 cycles earlier.
// Tail: ig*h and (1-ig) formed off-path after tanh(iv); terminus = 1 FMA.
__global__ void __launch_bounds__(32, 1) hypergru_rnn_kernel(
    const float* __restrict__ x,      // [B,1,T]
    const float* __restrict__ c,      // [B,8]
    const float* __restrict__ h0,     // [1,B,R]
    const float* __restrict__ mlp_w1, const float* __restrict__ mlp_b1,
    const float* __restrict__ mlp_w2, const float* __restrict__ mlp_b2,
    const float* __restrict__ pih_w,  const float* __restrict__ pih_b,
    const float* __restrict__ phh_w,  const float* __restrict__ phh_b,
    const float* __restrict__ pbih_w, const float* __restrict__ pbih_b,
    const float* __restrict__ pbhh_w, const float* __restrict__ pbhh_b,
    float* __restrict__ out)          // only h_last region written here
{
    const int b    = blockIdx.x;
    const int lane = threadIdx.x;
    const int j    = lane & 15;
    const int koff = (lane >> 4) * 8;

    // ---------------- hypernetwork prologue ----------------
    float cv[8];
#pragma unroll
    for (int k = 0; k < 8; ++k) cv[k] = c[b * 8 + k];
    float w1[8];
#pragma unroll
    for (int m = 0; m < 8; ++m) {
        float a = mlp_b1[m];
#pragma unroll
        for (int k = 0; k < 8; ++k) a = fmaf(cv[k], mlp_w1[m * 8 + k], a);
        w1[m] = lrelu(a);
    }
    float w2[8];
#pragma unroll
    for (int m = 0; m < 8; ++m) {
        float a = mlp_b2[m];
#pragma unroll
        for (int k = 0; k < 8; ++k) a = fmaf(w1[k], mlp_w2[m * 8 + k], a);
        w2[m] = lrelu(a);
    }
    auto proj8 = [&](const float* __restrict__ wrow, float bias) -> float {
        float a = bias;
#pragma unroll
        for (int k = 0; k < 8; ++k) a = fmaf(w2[k], wrow[k], a);
        return a;
    };

    // Recurrent weights for this lane's 8 k-terms.
    // r/i weights pre-halved (sigmoid via 0.5*tanh(v/2)+0.5).
    float whr_h[8], whi_h[8], whn[8];
#pragma unroll
    for (int k = 0; k < 8; ++k) {
        const int kk = k + koff;
        whr_h[k] = 0.5f * proj8(phh_w + (size_t)(kk * 48 + j) * 8,      phh_b[kk * 48 + j]);
        whi_h[k] = 0.5f * proj8(phh_w + (size_t)(kk * 48 + 16 + j) * 8, phh_b[kk * 48 + 16 + j]);
        whn[k]   =        proj8(phh_w + (size_t)(kk * 48 + 32 + j) * 8, phh_b[kk * 48 + 32 + j]);
    }
    const float bih_r = proj8(pbih_w + (size_t)j * 8,        pbih_b[j]);
    const float bih_i = proj8(pbih_w + (size_t)(16 + j) * 8, pbih_b[16 + j]);
    const float bhh_r = proj8(pbhh_w + (size_t)j * 8,        pbhh_b[j]);
    const float bhh_i = proj8(pbhh_w + (size_t)(16 + j) * 8, pbhh_b[16 + j]);

    // quarter-scaled seeds: each half seeds 0.25*(term); xor-combine doubles.
    const float wih_r_q = 0.25f * proj8(pih_w + (size_t)j * 8,        pih_b[j]);
    const float wih_i_q = 0.25f * proj8(pih_w + (size_t)(16 + j) * 8, pih_b[16 + j]);
    const float wih_n   =         proj8(pih_w + (size_t)(32 + j) * 8, pih_b[32 + j]);
    const float cbr_q   = 0.25f * (bih_r + bhh_r);
    const float cbi_q   = 0.25f * (bih_i + bhh_i);
    const float bih_n   = proj8(pbih_w + (size_t)(32 + j) * 8, pbih_b[32 + j]);
    const float bhh_n_h = 0.5f * proj8(pbhh_w + (size_t)(32 + j) * 8, pbhh_b[32 + j]);

    // ---------------- recurrence ----------------
    float h = h0[b * R + j];
    const float* __restrict__ xp = x + (size_t)b * T;
    float* __restrict__ hsp = g_hs + (size_t)b * T * R + j;   // contiguous per step

    float xq = xp[lane];   // 32 timesteps staged per lane
    for (int t0 = 0; t0 < T; t0 += 32) {
        const float xnext = (t0 + 32 < T) ? xp[t0 + 32 + lane] : 0.f;   // prefetch
        for (int tb = 0; tb < 32; tb += 8) {
#pragma unroll
            for (int tt = 0; tt < 8; ++tt) {
                const int ti = tb + tt;
                const float xt = __shfl_sync(FULLMASK, xq, ti, 32);
                const float hh = 0.5f * h;            // early; hidden under gathers

                // gather this half's 8 h-values
                float hrv[8];
#pragma unroll
                for (int k = 0; k < 8; ++k)
                    hrv[k] = __shfl_sync(FULLMASK, h, k + koff, 16);

                const float seed_r = fmaf(xt, wih_r_q, cbr_q);
                const float seed_i = fmaf(xt, wih_i_q, cbi_q);

                // single 8-deep chains (arrival-limited; no combine adds)
                float rp = fmaf(hrv[0], whr_h[0], seed_r);
                float ip = fmaf(hrv[0], whi_h[0], seed_i);
                float np = fmaf(hrv[0], whn[0],   bhh_n_h);
#pragma unroll
                for (int k = 1; k < 8; ++k) {
                    rp = fmaf(hrv[k], whr_h[k], rp);
                    ip = fmaf(hrv[k], whi_h[k], ip);
                    np = fmaf(hrv[k], whn[k],   np);
                }
                const float rf = rp + __shfl_xor_sync(FULLMASK, rp, 16);  // 0.5*preact_r
                const float hn = np + __shfl_xor_sync(FULLMASK, np, 16);  // full n hh-sum + bhh_n
                const float iv = ip + __shfl_xor_sync(FULLMASK, ip, 16);  // 0.5*preact_i

                // tanh(rf) first: its result is needed earliest (ng chain)
                const float tr  = tanh_fast(rf);                  // = 2*rg - 1
                const float i_n = fmaf(xt, wih_n, bih_n);
                const float inp = fmaf(0.5f, hn, i_n);            // i_n + 0.5*hn
                const float tv  = tanh_fast(iv);                  // = 2*ig - 1
                const float igh  = fmaf(tv, hh, hh);              // ig*h   (off-path)
                const float omig = fmaf(tv, -0.5f, 0.5f);         // 1 - ig (off-path)
                const float ng  = tanh_fast(fmaf(tr, 0.5f * hn, inp));
                h = fmaf(omig, ng, igh);                          // single FMA after ng

                if (lane < 16) hsp[(size_t)(t0 + ti) * R] = h;    // 64B contiguous line
            }
        }
        xq = xnext;
    }

    if (lane < 16) out[(size_t)B * T + b * R + j] = h;
}

// Pass 2: y[b,t] = dot(hs[b,t,:], out_w) + out_b  (bandwidth-bound, parallel)
__global__ void __launch_bounds__(256) out_proj_kernel(
    const float* __restrict__ out_w, const float* __restrict__ out_b,
    float* __restrict__ out)
{
    const int idx = blockIdx.x * 256 + threadIdx.x;   // idx = b*T + t
    const float4* __restrict__ hp = reinterpret_cast<const float4*>(g_hs) + (size_t)idx * 4;
    float4 v0 = hp[0], v1 = hp[1], v2 = hp[2], v3 = hp[3];
    const float4* __restrict__ wp = reinterpret_cast<const float4*>(out_w);
    float4 w0 = __ldg(wp), w1 = __ldg(wp + 1), w2 = __ldg(wp + 2), w3 = __ldg(wp + 3);

    float a = __ldg(out_b);
    a = fmaf(v0.x, w0.x, a); a = fmaf(v0.y, w0.y, a); a = fmaf(v0.z, w0.z, a); a = fmaf(v0.w, w0.w, a);
    a = fmaf(v1.x, w1.x, a); a = fmaf(v1.y, w1.y, a); a = fmaf(v1.z, w1.z, a); a = fmaf(v1.w, w1.w, a);
    a = fmaf(v2.x, w2.x, a); a = fmaf(v2.y, w2.y, a); a = fmaf(v2.z, w2.z, a); a = fmaf(v2.w, w2.w, a);
    a = fmaf(v3.x, w3.x, a); a = fmaf(v3.y, w3.y, a); a = fmaf(v3.z, w3.z, a); a = fmaf(v3.w, w3.w, a);
    out[idx] = a;
}

extern "C" void kernel_launch(void* const* d_in, const int* in_sizes, int n_in,
                              void* d_out, int out_size) {
    (void)in_sizes; (void)n_in; (void)out_size;
    hypergru_rnn_kernel<<<B, 32>>>(
        (const float*)d_in[0],  (const float*)d_in[1],  (const float*)d_in[2],
        (const float*)d_in[3],  (const float*)d_in[4],  (const float*)d_in[5],
        (const float*)d_in[6],  (const float*)d_in[7],  (const float*)d_in[8],
        (const float*)d_in[9],  (const float*)d_in[10], (const float*)d_in[11],
        (const float*)d_in[12], (const float*)d_in[13], (const float*)d_in[14],
        (float*)d_out);
    out_proj_kernel<<<(B * T) / 256, 256>>>(
        (const float*)d_in[15], (const float*)d_in[16], (float*)d_out);
}

// round 17
// speedup vs baseline: 1.0286x; 1.0286x over previous
#include <cuda_runtime.h>
#include <cuda_bf16.h>

#define FULLMASK 0xffffffffu

namespace {
constexpr int B = 64;
constexpr int T = 32768;
constexpr int R = 16;
}

// Scratch: hidden states for all steps, layout [B][T][R] (contiguous per step).
__device__ float g_hs[(size_t)B * T * R];   // 128 MiB

__device__ __forceinline__ float lrelu(float v) { return v >= 0.f ? v : 0.1f * v; }
__device__ __forceinline__ float tanh_fast(float v) {
    float r;
    asm("tanh.approx.f32 %0, %1;" : "=f"(r) : "f"(v));
    return r;
}

// One warp per sample. Lane (g, j): g = lane>>4, j = lane&15.
// Lane owns hidden unit j; half g sums k = 8g..8g+7 of each gate (split-k),
// halves combined with one shfl_xor(16) per gate.
// Chain shapes by criticality: r-gate (feeds tanh->fma->tanh, zero slack) uses
// the 2-acc split for scheduling freedom; i/n gates (slack after xor) use
// single 8-deep chains, deleting their combine adds.
// Tail: ig*h and (1-ig) formed off-path after tanh(iv); terminus = 1 FMA.
__global__ void __launch_bounds__(32, 1) hypergru_rnn_kernel(
    const float* __restrict__ x,      // [B,1,T]
    const float* __restrict__ c,      // [B,8]
    const float* __restrict__ h0,     // [1,B,R]
    const float* __restrict__ mlp_w1, const float* __restrict__ mlp_b1,
    const float* __restrict__ mlp_w2, const float* __restrict__ mlp_b2,
    const float* __restrict__ pih_w,  const float* __restrict__ pih_b,
    const float* __restrict__ phh_w,  const float* __restrict__ phh_b,
    const float* __restrict__ pbih_w, const float* __restrict__ pbih_b,
    const float* __restrict__ pbhh_w, const float* __restrict__ pbhh_b,
    float* __restrict__ out)          // only h_last region written here
{
    const int b    = blockIdx.x;
    const int lane = threadIdx.x;
    const int j    = lane & 15;
    const int koff = (lane >> 4) * 8;

    // ---------------- hypernetwork prologue ----------------
    float cv[8];
#pragma unroll
    for (int k = 0; k < 8; ++k) cv[k] = c[b * 8 + k];
    float w1[8];
#pragma unroll
    for (int m = 0; m < 8; ++m) {
        float a = mlp_b1[m];
#pragma unroll
        for (int k = 0; k < 8; ++k) a = fmaf(cv[k], mlp_w1[m * 8 + k], a);
        w1[m] = lrelu(a);
    }
    float w2[8];
#pragma unroll
    for (int m = 0; m < 8; ++m) {
        float a = mlp_b2[m];
#pragma unroll
        for (int k = 0; k < 8; ++k) a = fmaf(w1[k], mlp_w2[m * 8 + k], a);
        w2[m] = lrelu(a);
    }
    auto proj8 = [&](const float* __restrict__ wrow, float bias) -> float {
        float a = bias;
#pragma unroll
        for (int k = 0; k < 8; ++k) a = fmaf(w2[k], wrow[k], a);
        return a;
    };

    // Recurrent weights for this lane's 8 k-terms.
    // r/i weights pre-halved (sigmoid via 0.5*tanh(v/2)+0.5).
    float whr_h[8], whi_h[8], whn[8];
#pragma unroll
    for (int k = 0; k < 8; ++k) {
        const int kk = k + koff;
        whr_h[k] = 0.5f * proj8(phh_w + (size_t)(kk * 48 + j) * 8,      phh_b[kk * 48 + j]);
        whi_h[k] = 0.5f * proj8(phh_w + (size_t)(kk * 48 + 16 + j) * 8, phh_b[kk * 48 + 16 + j]);
        whn[k]   =        proj8(phh_w + (size_t)(kk * 48 + 32 + j) * 8, phh_b[kk * 48 + 32 + j]);
    }
    const float bih_r = proj8(pbih_w + (size_t)j * 8,        pbih_b[j]);
    const float bih_i = proj8(pbih_w + (size_t)(16 + j) * 8, pbih_b[16 + j]);
    const float bhh_r = proj8(pbhh_w + (size_t)j * 8,        pbhh_b[j]);
    const float bhh_i = proj8(pbhh_w + (size_t)(16 + j) * 8, pbhh_b[16 + j]);

    // quarter-scaled seeds: each half seeds 0.25*(term); xor-combine doubles.
    const float wih_r_q = 0.25f * proj8(pih_w + (size_t)j * 8,        pih_b[j]);
    const float wih_i_q = 0.25f * proj8(pih_w + (size_t)(16 + j) * 8, pih_b[16 + j]);
    const float wih_n   =         proj8(pih_w + (size_t)(32 + j) * 8, pih_b[32 + j]);
    const float cbr_q   = 0.25f * (bih_r + bhh_r);
    const float cbi_q   = 0.25f * (bih_i + bhh_i);
    const float bih_n   = proj8(pbih_w + (size_t)(32 + j) * 8, pbih_b[32 + j]);
    const float bhh_n_h = 0.5f * proj8(pbhh_w + (size_t)(32 + j) * 8, pbhh_b[32 + j]);

    // ---------------- recurrence ----------------
    float h = h0[b * R + j];
    const float* __restrict__ xp = x + (size_t)b * T;
    float* __restrict__ hsp = g_hs + (size_t)b * T * R + j;   // contiguous per step

    float xq = xp[lane];   // 32 timesteps staged per lane
    for (int t0 = 0; t0 < T; t0 += 32) {
        const float xnext = (t0 + 32 < T) ? xp[t0 + 32 + lane] : 0.f;   // prefetch
        for (int tb = 0; tb < 32; tb += 8) {
#pragma unroll
            for (int tt = 0; tt < 8; ++tt) {
                const int ti = tb + tt;
                const float xt = __shfl_sync(FULLMASK, xq, ti, 32);
                const float hh = 0.5f * h;            // early; hidden under gathers

                // gather this half's 8 h-values
                float hrv[8];
#pragma unroll
                for (int k = 0; k < 8; ++k)
                    hrv[k] = __shfl_sync(FULLMASK, h, k + koff, 16);

                const float seed_r = fmaf(xt, wih_r_q, cbr_q);
                const float seed_i = fmaf(xt, wih_i_q, cbi_q);

                // r: 2-acc split (critical path, scheduling freedom)
                float r0 = fmaf(hrv[0], whr_h[0], seed_r);
                float r1 = hrv[4] * whr_h[4];
                // i/n: single 8-deep chains (slack-tolerant; no combine adds)
                float ip = fmaf(hrv[0], whi_h[0], seed_i);
                float np = fmaf(hrv[0], whn[0],   bhh_n_h);
#pragma unroll
                for (int k = 1; k < 4; ++k) {
                    r0 = fmaf(hrv[k],     whr_h[k],     r0);
                    r1 = fmaf(hrv[k + 4], whr_h[k + 4], r1);
                }
#pragma unroll
                for (int k = 1; k < 8; ++k) {
                    ip = fmaf(hrv[k], whi_h[k], ip);
                    np = fmaf(hrv[k], whn[k],   np);
                }
                const float rp = r0 + r1;
                const float rf = rp + __shfl_xor_sync(FULLMASK, rp, 16);  // 0.5*preact_r
                const float hn = np + __shfl_xor_sync(FULLMASK, np, 16);  // full n hh-sum + bhh_n
                const float iv = ip + __shfl_xor_sync(FULLMASK, ip, 16);  // 0.5*preact_i

                // tanh(rf) first: its result is needed earliest (ng chain)
                const float tr  = tanh_fast(rf);                  // = 2*rg - 1
                const float i_n = fmaf(xt, wih_n, bih_n);
                const float inp = fmaf(0.5f, hn, i_n);            // i_n + 0.5*hn
                const float tv  = tanh_fast(iv);                  // = 2*ig - 1
                const float igh  = fmaf(tv, hh, hh);              // ig*h   (off-path)
                const float omig = fmaf(tv, -0.5f, 0.5f);         // 1 - ig (off-path)
                const float ng  = tanh_fast(fmaf(tr, 0.5f * hn, inp));
                h = fmaf(omig, ng, igh);                          // single FMA after ng

                if (lane < 16) hsp[(size_t)(t0 + ti) * R] = h;    // 64B contiguous line
            }
        }
        xq = xnext;
    }

    if (lane < 16) out[(size_t)B * T + b * R + j] = h;
}

// Pass 2: y[b,t] = dot(hs[b,t,:], out_w) + out_b  (bandwidth-bound, parallel)
__global__ void __launch_bounds__(256) out_proj_kernel(
    const float* __restrict__ out_w, const float* __restrict__ out_b,
    float* __restrict__ out)
{
    const int idx = blockIdx.x * 256 + threadIdx.x;   // idx = b*T + t
    const float4* __restrict__ hp = reinterpret_cast<const float4*>(g_hs) + (size_t)idx * 4;
    float4 v0 = hp[0], v1 = hp[1], v2 = hp[2], v3 = hp[3];
    const float4* __restrict__ wp = reinterpret_cast<const float4*>(out_w);
    float4 w0 = __ldg(wp), w1 = __ldg(wp + 1), w2 = __ldg(wp + 2), w3 = __ldg(wp + 3);

    float a = __ldg(out_b);
    a = fmaf(v0.x, w0.x, a); a = fmaf(v0.y, w0.y, a); a = fmaf(v0.z, w0.z, a); a = fmaf(v0.w, w0.w, a);
    a = fmaf(v1.x, w1.x, a); a = fmaf(v1.y, w1.y, a); a = fmaf(v1.z, w1.z, a); a = fmaf(v1.w, w1.w, a);
    a = fmaf(v2.x, w2.x, a); a = fmaf(v2.y, w2.y, a); a = fmaf(v2.z, w2.z, a); a = fmaf(v2.w, w2.w, a);
    a = fmaf(v3.x, w3.x, a); a = fmaf(v3.y, w3.y, a); a = fmaf(v3.z, w3.z, a); a = fmaf(v3.w, w3.w, a);
    out[idx] = a;
}

extern "C" void kernel_launch(void* const* d_in, const int* in_sizes, int n_in,
                              void* d_out, int out_size) {
    (void)in_sizes; (void)n_in; (void)out_size;
    hypergru_rnn_kernel<<<B, 32>>>(
        (const float*)d_in[0],  (const float*)d_in[1],  (const float*)d_in[2],
        (const float*)d_in[3],  (const float*)d_in[4],  (const float*)d_in[5],
        (const float*)d_in[6],  (const float*)d_in[7],  (const float*)d_in[8],
        (const float*)d_in[9],  (const float*)d_in[10], (const float*)d_in[11],
        (const float*)d_in[12], (const float*)d_in[13], (const float*)d_in[14],
        (float*)d_out);
    out_proj_kernel<<<(B * T) / 256, 256>>>(
        (const float*)d_in[15], (const float*)d_in[16], (float*)d_out);
}